// round 7
// baseline (speedup 1.0000x reference)
#include <cuda_runtime.h>
#include <cuda_bf16.h>
#include <float.h>

// B=4. Per query: argmin over anchors of d' = a2 - 2*q.a (same argmin as
// squared distance; exact first-index tie-break via (fkey<<32|idx) min),
// then count dot(diff, summed face normal) < 0 within MAX_DIST. Normal
// normalization is a positive scaling -> sign unchanged -> raw summed face
// normals suffice.
//
// NN: anchors AND queries counting-sorted by 32^3 cell. Each warp owns 32
// consecutive sorted queries (tight cell bbox). Warp-uniform expanding-cube
// scan of sorted-anchor cell runs; lanes broadcast-read candidates and
// key-min their own query. Per-lane stop bound: true d2 vs distance to
// scanned-box faces (grid-edge faces = infinity, which also covers clamped
// outliers). Exact.

#define NB      4
#define GDIM    32
#define NCELL   (GDIM * GDIM * GDIM)
#define NCELL1  (NCELL + 1)
#define MAXA    8192
#define MAXQ    16384
#define GX0     (-5.0f)
#define CH      0.3125f
#define INVH    3.2f

typedef unsigned long long u64;

__device__ int    g_Acnt[NB * NCELL];
__device__ int    g_Qcnt[NB * NCELL];
__device__ int    g_Astart[NB * NCELL1];
__device__ int    g_Acur[NB * NCELL];
__device__ int    g_Qstart[NB * NCELL1];
__device__ int    g_Qcur[NB * NCELL];
__device__ float4 g_As[NB * MAXA];    // sorted anchors: (wx,wy,wz,ww)=(-2a,a2)
__device__ int    g_Ai[NB * MAXA];    // sorted slot -> original anchor idx
__device__ float4 g_Qs[NB * MAXQ];    // sorted queries (x,y,z,0)
__device__ float  g_acc[NB * MAXA * 3];

__device__ __forceinline__ int clampi(int v, int lo, int hi) {
    return v < lo ? lo : (v > hi ? hi : v);
}
__device__ __forceinline__ void cell3(float x, float y, float z,
                                      int& cx, int& cy, int& cz) {
    cx = clampi(__float2int_rd((x - GX0) * INVH), 0, GDIM - 1);
    cy = clampi(__float2int_rd((y - GX0) * INVH), 0, GDIM - 1);
    cz = clampi(__float2int_rd((z - GX0) * INVH), 0, GDIM - 1);
}
__device__ __forceinline__ int cell_of(float x, float y, float z) {
    int cx, cy, cz;
    cell3(x, y, z, cx, cy, cz);
    return (cz * GDIM + cy) * GDIM + cx;
}
// Monotone float-bits -> u32 key (smaller float -> smaller key). No NaNs.
__device__ __forceinline__ unsigned fkey(float f) {
    unsigned b = __float_as_uint(f);
    return (b & 0x80000000u) ? ~b : (b | 0x80000000u);
}

// ---------------------------------------------------------------------------
// K0: zero everything written by atomics later
// ---------------------------------------------------------------------------
__global__ void zero_kernel(float* __restrict__ out)
{
    int i = blockIdx.x * blockDim.x + threadIdx.x;
    if (i < NB) out[i] = 0.0f;
    if (i < NB * NCELL) { g_Acnt[i] = 0; g_Qcnt[i] = 0; }
    if (i < NB * MAXA * 3) g_acc[i] = 0.0f;
}

// ---------------------------------------------------------------------------
// K1: count anchors + queries per cell, and face-normal scatter-add (fused)
// ---------------------------------------------------------------------------
__global__ void count_face_kernel(const float* __restrict__ anchor,
                                  const float* __restrict__ query,
                                  const int* __restrict__ faces,
                                  int Na, int Nq, int F)
{
    int i = blockIdx.x * blockDim.x + threadIdx.x;
    int totA = NB * Na;
    if (i < totA) {
        int b = i / Na;
        int c = cell_of(anchor[3 * i], anchor[3 * i + 1], anchor[3 * i + 2]);
        atomicAdd(&g_Acnt[b * NCELL + c], 1);
        return;
    }
    int j = i - totA;
    if (j < NB * Nq) {
        int b = j / Nq;
        int c = cell_of(query[3 * j], query[3 * j + 1], query[3 * j + 2]);
        atomicAdd(&g_Qcnt[b * NCELL + c], 1);
        return;
    }
    int k = j - NB * Nq;
    if (k >= NB * F) return;
    int b = k / F;
    int f = k - b * F;

    int i0 = faces[3 * f + 0];
    int i1 = faces[3 * f + 1];
    int i2 = faces[3 * f + 2];

    const float* base = anchor + (size_t)b * Na * 3;
    float v0x = base[3 * i0 + 0], v0y = base[3 * i0 + 1], v0z = base[3 * i0 + 2];
    float v1x = base[3 * i1 + 0], v1y = base[3 * i1 + 1], v1z = base[3 * i1 + 2];
    float v2x = base[3 * i2 + 0], v2y = base[3 * i2 + 1], v2z = base[3 * i2 + 2];

    float e1x = v1x - v0x, e1y = v1y - v0y, e1z = v1z - v0z;
    float e2x = v2x - v0x, e2y = v2y - v0y, e2z = v2z - v0z;

    float nx = e1y * e2z - e1z * e2y;
    float ny = e1z * e2x - e1x * e2z;
    float nz = e1x * e2y - e1y * e2x;

    float* acc = g_acc + (size_t)b * MAXA * 3;
    atomicAdd(&acc[3 * i0 + 0], nx);
    atomicAdd(&acc[3 * i0 + 1], ny);
    atomicAdd(&acc[3 * i0 + 2], nz);
    atomicAdd(&acc[3 * i1 + 0], nx);
    atomicAdd(&acc[3 * i1 + 1], ny);
    atomicAdd(&acc[3 * i1 + 2], nz);
    atomicAdd(&acc[3 * i2 + 0], nx);
    atomicAdd(&acc[3 * i2 + 1], ny);
    atomicAdd(&acc[3 * i2 + 2], nz);
}

// ---------------------------------------------------------------------------
// K2: exclusive scan of 32768 counts per (batch, kind). 8 blocks x 1024 thr.
// ---------------------------------------------------------------------------
__global__ void __launch_bounds__(1024)
scan_kernel()
{
    __shared__ int sp[1024];
    int which = blockIdx.x;            // 0..3 anchors, 4..7 queries
    int b = which & 3;
    bool isQ = which >= 4;
    const int* cnt = (isQ ? g_Qcnt : g_Acnt) + b * NCELL;
    int* start = (isQ ? g_Qstart : g_Astart) + b * NCELL1;
    int* cur   = (isQ ? g_Qcur   : g_Acur)   + b * NCELL;

    int t = threadIdx.x;
    int c0 = t * 32;
    int loc[32];
    int s = 0;
    #pragma unroll
    for (int i = 0; i < 32; i++) { loc[i] = s; s += cnt[c0 + i]; }
    sp[t] = s;
    __syncthreads();
    for (int off = 1; off < 1024; off <<= 1) {
        int v = (t >= off) ? sp[t - off] : 0;
        __syncthreads();
        sp[t] += v;
        __syncthreads();
    }
    int base = sp[t] - s;
    #pragma unroll
    for (int i = 0; i < 32; i++) {
        int v = base + loc[i];
        start[c0 + i] = v;
        cur[c0 + i] = v;
    }
    if (t == 1023) start[NCELL] = sp[1023];
}

// ---------------------------------------------------------------------------
// K3: scatter anchors (weights + orig idx) and queries into sorted order
// ---------------------------------------------------------------------------
__global__ void scatter_kernel(const float* __restrict__ anchor,
                               const float* __restrict__ query,
                               int Na, int Nq)
{
    int i = blockIdx.x * blockDim.x + threadIdx.x;
    int totA = NB * Na;
    if (i < totA) {
        int b = i / Na;
        int a = i - b * Na;
        float x = anchor[3 * i], y = anchor[3 * i + 1], z = anchor[3 * i + 2];
        int c = cell_of(x, y, z);
        int pos = atomicAdd(&g_Acur[b * NCELL + c], 1);
        g_As[b * MAXA + pos] = make_float4(-2.0f * x, -2.0f * y, -2.0f * z,
                                           x * x + y * y + z * z);
        g_Ai[b * MAXA + pos] = a;
        return;
    }
    int j = i - totA;
    if (j >= NB * Nq) return;
    int b = j / Nq;
    float x = query[3 * j], y = query[3 * j + 1], z = query[3 * j + 2];
    int c = cell_of(x, y, z);
    int pos = atomicAdd(&g_Qcur[b * NCELL + c], 1);
    g_Qs[b * MAXQ + pos] = make_float4(x, y, z, 0.0f);
}

// ---------------------------------------------------------------------------
// K4: warp-cooperative grid NN + collision count.
// Each warp: 32 consecutive sorted queries; warp-uniform expanding-cube scan.
// ---------------------------------------------------------------------------
__global__ void __launch_bounds__(128)
nn_kernel(const float* __restrict__ anchor, float* __restrict__ out,
          int Nq, int Na)
{
    int b = blockIdx.y;
    int s = blockIdx.x * 128 + threadIdx.x;
    bool valid = (s < Nq);
    int sc = valid ? s : (Nq - 1);

    float4 qv = g_Qs[b * MAXQ + sc];
    float qx = qv.x, qy = qv.y, qz = qv.z;
    float q2 = qx * qx + qy * qy + qz * qz;

    int cx, cy, cz;
    cell3(qx, qy, qz, cx, cy, cz);

    // warp bbox of query cells
    int bx0 = cx, bx1 = cx, by0 = cy, by1 = cy, bz0 = cz, bz1 = cz;
    #pragma unroll
    for (int o = 16; o >= 1; o >>= 1) {
        bx0 = min(bx0, __shfl_xor_sync(0xFFFFFFFFu, bx0, o));
        bx1 = max(bx1, __shfl_xor_sync(0xFFFFFFFFu, bx1, o));
        by0 = min(by0, __shfl_xor_sync(0xFFFFFFFFu, by0, o));
        by1 = max(by1, __shfl_xor_sync(0xFFFFFFFFu, by1, o));
        bz0 = min(bz0, __shfl_xor_sync(0xFFFFFFFFu, bz0, o));
        bz1 = max(bz1, __shfl_xor_sync(0xFFFFFFFFu, bz1, o));
    }

    const int*    Astart = g_Astart + b * NCELL1;
    const float4* As     = g_As + (size_t)b * MAXA;
    const int*    Ai     = g_Ai + (size_t)b * MAXA;

    u64 kbest = 0xFFFFFFFFFFFFFFFFull;
    float dbest = FLT_MAX;

    int px0 = 1, px1 = 0, py0 = 1, py1 = 0, pz0 = 1, pz1 = 0;  // empty

    for (int e = 1; e <= GDIM; e++) {
        int nx0 = max(bx0 - e, 0), nx1 = min(bx1 + e, GDIM - 1);
        int ny0 = max(by0 - e, 0), ny1 = min(by1 + e, GDIM - 1);
        int nz0 = max(bz0 - e, 0), nz1 = min(bz1 + e, GDIM - 1);

        for (int z = nz0; z <= nz1; z++) {
            bool zin = (z >= pz0 && z <= pz1);
            for (int y = ny0; y <= ny1; y++) {
                bool rowPrev = zin && (y >= py0 && y <= py1);
                int rowc = (z * GDIM + y) * GDIM;
                for (int x = nx0; x <= nx1; x++) {
                    if (rowPrev && x >= px0 && x <= px1) { x = px1; continue; }
                    int c = rowc + x;
                    int p0 = Astart[c];
                    int p1 = Astart[c + 1];
                    int p = p0;
                    for (; p + 2 <= p1; p += 2) {
                        float4 w0 = As[p];
                        float4 w1 = As[p + 1];
                        int a0 = Ai[p];
                        int a1 = Ai[p + 1];
                        float d0 = fmaf(w0.x, qx, fmaf(w0.y, qy, fmaf(w0.z, qz, w0.w)));
                        float d1 = fmaf(w1.x, qx, fmaf(w1.y, qy, fmaf(w1.z, qz, w1.w)));
                        u64 k0 = ((u64)fkey(d0) << 32) | (unsigned)a0;
                        u64 k1 = ((u64)fkey(d1) << 32) | (unsigned)a1;
                        if (k0 < kbest) { kbest = k0; dbest = d0; }
                        if (k1 < kbest) { kbest = k1; dbest = d1; }
                    }
                    if (p < p1) {
                        float4 w = As[p];
                        int a0 = Ai[p];
                        float d = fmaf(w.x, qx, fmaf(w.y, qy, fmaf(w.z, qz, w.w)));
                        u64 k = ((u64)fkey(d) << 32) | (unsigned)a0;
                        if (k < kbest) { kbest = k; dbest = d; }
                    }
                }
            }
        }

        // per-lane stop bound: true d2 vs distance to scanned-box faces
        float dlx = (nx0 == 0)        ? FLT_MAX : qx - (GX0 + nx0 * CH);
        float dhx = (nx1 == GDIM - 1) ? FLT_MAX : (GX0 + (nx1 + 1) * CH) - qx;
        float dly = (ny0 == 0)        ? FLT_MAX : qy - (GX0 + ny0 * CH);
        float dhy = (ny1 == GDIM - 1) ? FLT_MAX : (GX0 + (ny1 + 1) * CH) - qy;
        float dlz = (nz0 == 0)        ? FLT_MAX : qz - (GX0 + nz0 * CH);
        float dhz = (nz1 == GDIM - 1) ? FLT_MAX : (GX0 + (nz1 + 1) * CH) - qz;
        float dout = fminf(fminf(fminf(dlx, dhx), fminf(dly, dhy)),
                           fminf(dlz, dhz));
        bool done = (dbest + q2 + 1e-4f <= dout * dout);
        if (__all_sync(0xFFFFFFFFu, done)) break;
        if (nx0 == 0 && nx1 == GDIM - 1 && ny0 == 0 && ny1 == GDIM - 1 &&
            nz0 == 0 && nz1 == GDIM - 1) break;   // whole grid scanned

        px0 = nx0; px1 = nx1; py0 = ny0; py1 = ny1; pz0 = nz0; pz1 = nz1;
    }

    int best = (int)(unsigned)(kbest & 0xFFFFFFFFull);

    const float* ap = anchor + ((size_t)b * Na + best) * 3;
    float dx = qx - ap[0];
    float dy = qy - ap[1];
    float dz = qz - ap[2];

    const float* npx = g_acc + ((size_t)b * MAXA + best) * 3;
    float dot = dx * npx[0] + dy * npx[1] + dz * npx[2];
    float l2  = sqrtf(dx * dx + dy * dy + dz * dz);

    int coll = (valid && (l2 <= 5.0f) && (dot < 0.0f)) ? 1 : 0;
    unsigned m = __ballot_sync(0xFFFFFFFFu, coll);
    if ((threadIdx.x & 31) == 0 && m)
        atomicAdd(&out[b], (float)__popc(m));
}

// ---------------------------------------------------------------------------
extern "C" void kernel_launch(void* const* d_in, const int* in_sizes, int n_in,
                              void* d_out, int out_size)
{
    const float* query  = (const float*)d_in[0];
    const float* anchor = (const float*)d_in[1];
    const int*   faces  = (const int*)d_in[2];
    float* out = (float*)d_out;

    int Nq = in_sizes[0] / (NB * 3);
    int Na = in_sizes[1] / (NB * 3);
    int F  = in_sizes[2] / 3;

    int zn = NB * NCELL;
    if (NB * MAXA * 3 > zn) zn = NB * MAXA * 3;
    zero_kernel<<<(zn + 255) / 256, 256>>>(out);

    int cn = NB * (Na + Nq + F);
    count_face_kernel<<<(cn + 255) / 256, 256>>>(anchor, query, faces, Na, Nq, F);

    scan_kernel<<<8, 1024>>>();

    int sn = NB * (Na + Nq);
    scatter_kernel<<<(sn + 255) / 256, 256>>>(anchor, query, Na, Nq);

    dim3 ngrid((Nq + 127) / 128, NB);
    nn_kernel<<<ngrid, 128>>>(anchor, out, Nq, Na);
}

// round 8
// speedup vs baseline: 10.9621x; 10.9621x over previous
#include <cuda_runtime.h>
#include <cuda_bf16.h>
#include <float.h>

// B=4. Per query: argmin over anchors of d' = a2 - 2*q.a (same argmin as
// squared distance; first-index tie-break preserved exactly), then count
// dot(diff, summed face normal) < 0 within MAX_DIST. Normal normalization is
// a positive scaling -> sign unchanged -> raw summed face normals suffice.
//
// NN: anchors + queries counting-sorted by 32^3 cell. Each lane scans the 9
// contiguous sorted-anchor runs of its query's 3x3x3 cell box (~130 cands),
// then checks a sound distance-to-box-face certificate. Uncertified queries
// (sparse tail, ~1-4%) are compacted and resolved by an exact warp-per-query
// brute-force kernel. Every path is exact.

#define NB      4
#define GDIM    32
#define NCELL   (GDIM * GDIM * GDIM)
#define NCELL1  (NCELL + 1)
#define MAXA    8192
#define MAXQ    16384
#define GX0     (-5.0f)
#define CH      0.3125f
#define INVH    3.2f
#define MARGIN  1e-3f

typedef unsigned long long u64;

__device__ int    g_Acnt[NB * NCELL];
__device__ int    g_Qcnt[NB * NCELL];
__device__ int    g_Astart[NB * NCELL1];
__device__ int    g_Acur[NB * NCELL];
__device__ int    g_Qstart[NB * NCELL1];
__device__ int    g_Qcur[NB * NCELL];
__device__ float4 g_As[NB * MAXA];   // sorted anchors: (wx,wy,wz,ww)=(-2a,a2)
__device__ int    g_Ai[NB * MAXA];   // sorted slot -> original anchor idx
__device__ float4 g_Qs[NB * MAXQ];   // sorted queries (x,y,z,0)
__device__ float  g_acc[NB * MAXA * 3];
__device__ int    g_fbcnt[NB];
__device__ int    g_fb[NB * MAXQ];

__device__ __forceinline__ int clampi(int v, int lo, int hi) {
    return v < lo ? lo : (v > hi ? hi : v);
}
__device__ __forceinline__ void cell3(float x, float y, float z,
                                      int& cx, int& cy, int& cz) {
    cx = clampi(__float2int_rd((x - GX0) * INVH), 0, GDIM - 1);
    cy = clampi(__float2int_rd((y - GX0) * INVH), 0, GDIM - 1);
    cz = clampi(__float2int_rd((z - GX0) * INVH), 0, GDIM - 1);
}
__device__ __forceinline__ int cell_of(float x, float y, float z) {
    int cx, cy, cz;
    cell3(x, y, z, cx, cy, cz);
    return (cz * GDIM + cy) * GDIM + cx;
}
// Monotone float-bits -> u32 key (smaller float -> smaller key). No NaNs.
__device__ __forceinline__ unsigned fkey(float f) {
    unsigned b = __float_as_uint(f);
    return (b & 0x80000000u) ? ~b : (b | 0x80000000u);
}

// ---------------------------------------------------------------------------
// K0: zero counters / accumulators / output / fallback counts
// ---------------------------------------------------------------------------
__global__ void zero_kernel(float* __restrict__ out)
{
    int i = blockIdx.x * blockDim.x + threadIdx.x;
    if (i < NB) { out[i] = 0.0f; g_fbcnt[i] = 0; }
    if (i < NB * NCELL) { g_Acnt[i] = 0; g_Qcnt[i] = 0; }
    if (i < NB * MAXA * 3) g_acc[i] = 0.0f;
}

// ---------------------------------------------------------------------------
// K1: fused per-cell counting (anchors + queries) and face-normal scatter
// ---------------------------------------------------------------------------
__global__ void count_face_kernel(const float* __restrict__ anchor,
                                  const float* __restrict__ query,
                                  const int* __restrict__ faces,
                                  int Na, int Nq, int F)
{
    int i = blockIdx.x * blockDim.x + threadIdx.x;
    int totA = NB * Na;
    if (i < totA) {
        int b = i / Na;
        int c = cell_of(anchor[3 * i], anchor[3 * i + 1], anchor[3 * i + 2]);
        atomicAdd(&g_Acnt[b * NCELL + c], 1);
        return;
    }
    int j = i - totA;
    if (j < NB * Nq) {
        int b = j / Nq;
        int c = cell_of(query[3 * j], query[3 * j + 1], query[3 * j + 2]);
        atomicAdd(&g_Qcnt[b * NCELL + c], 1);
        return;
    }
    int k = j - NB * Nq;
    if (k >= NB * F) return;
    int b = k / F;
    int f = k - b * F;

    int i0 = faces[3 * f + 0];
    int i1 = faces[3 * f + 1];
    int i2 = faces[3 * f + 2];

    const float* base = anchor + (size_t)b * Na * 3;
    float v0x = base[3 * i0 + 0], v0y = base[3 * i0 + 1], v0z = base[3 * i0 + 2];
    float v1x = base[3 * i1 + 0], v1y = base[3 * i1 + 1], v1z = base[3 * i1 + 2];
    float v2x = base[3 * i2 + 0], v2y = base[3 * i2 + 1], v2z = base[3 * i2 + 2];

    float e1x = v1x - v0x, e1y = v1y - v0y, e1z = v1z - v0z;
    float e2x = v2x - v0x, e2y = v2y - v0y, e2z = v2z - v0z;

    float nx = e1y * e2z - e1z * e2y;
    float ny = e1z * e2x - e1x * e2z;
    float nz = e1x * e2y - e1y * e2x;

    float* acc = g_acc + (size_t)b * MAXA * 3;
    atomicAdd(&acc[3 * i0 + 0], nx);
    atomicAdd(&acc[3 * i0 + 1], ny);
    atomicAdd(&acc[3 * i0 + 2], nz);
    atomicAdd(&acc[3 * i1 + 0], nx);
    atomicAdd(&acc[3 * i1 + 1], ny);
    atomicAdd(&acc[3 * i1 + 2], nz);
    atomicAdd(&acc[3 * i2 + 0], nx);
    atomicAdd(&acc[3 * i2 + 1], ny);
    atomicAdd(&acc[3 * i2 + 2], nz);
}

// ---------------------------------------------------------------------------
// K2: exclusive scan of 32768 counts per (batch, kind). 8 blocks x 1024 thr.
// ---------------------------------------------------------------------------
__global__ void __launch_bounds__(1024)
scan_kernel()
{
    __shared__ int sp[1024];
    int which = blockIdx.x;            // 0..3 anchors, 4..7 queries
    int b = which & 3;
    bool isQ = which >= 4;
    const int* cnt = (isQ ? g_Qcnt : g_Acnt) + b * NCELL;
    int* start = (isQ ? g_Qstart : g_Astart) + b * NCELL1;
    int* cur   = (isQ ? g_Qcur   : g_Acur)   + b * NCELL;

    int t = threadIdx.x;
    int c0 = t * 32;
    int loc[32];
    int s = 0;
    #pragma unroll
    for (int i = 0; i < 32; i++) { loc[i] = s; s += cnt[c0 + i]; }
    sp[t] = s;
    __syncthreads();
    for (int off = 1; off < 1024; off <<= 1) {
        int v = (t >= off) ? sp[t - off] : 0;
        __syncthreads();
        sp[t] += v;
        __syncthreads();
    }
    int base = sp[t] - s;
    #pragma unroll
    for (int i = 0; i < 32; i++) {
        int v = base + loc[i];
        start[c0 + i] = v;
        cur[c0 + i] = v;
    }
    if (t == 1023) start[NCELL] = sp[1023];
}

// ---------------------------------------------------------------------------
// K3: scatter anchors (weights + orig idx) and queries into sorted order
// ---------------------------------------------------------------------------
__global__ void scatter_kernel(const float* __restrict__ anchor,
                               const float* __restrict__ query,
                               int Na, int Nq)
{
    int i = blockIdx.x * blockDim.x + threadIdx.x;
    int totA = NB * Na;
    if (i < totA) {
        int b = i / Na;
        int a = i - b * Na;
        float x = anchor[3 * i], y = anchor[3 * i + 1], z = anchor[3 * i + 2];
        int c = cell_of(x, y, z);
        int pos = atomicAdd(&g_Acur[b * NCELL + c], 1);
        g_As[b * MAXA + pos] = make_float4(-2.0f * x, -2.0f * y, -2.0f * z,
                                           x * x + y * y + z * z);
        g_Ai[b * MAXA + pos] = a;
        return;
    }
    int j = i - totA;
    if (j >= NB * Nq) return;
    int b = j / Nq;
    float x = query[3 * j], y = query[3 * j + 1], z = query[3 * j + 2];
    int c = cell_of(x, y, z);
    int pos = atomicAdd(&g_Qcur[b * NCELL + c], 1);
    g_Qs[b * MAXQ + pos] = make_float4(x, y, z, 0.0f);
}

// ---------------------------------------------------------------------------
// K4: per-lane 27-cell NN scan + certificate; fallback push if uncertified
// ---------------------------------------------------------------------------
__global__ void __launch_bounds__(128)
nn_kernel(const float* __restrict__ anchor, float* __restrict__ out,
          int Nq, int Na)
{
    int b = blockIdx.y;
    int s = blockIdx.x * 128 + threadIdx.x;
    bool valid = (s < Nq);
    int sc = valid ? s : (Nq - 1);

    float4 qv = g_Qs[b * MAXQ + sc];
    float qx = qv.x, qy = qv.y, qz = qv.z;
    float q2 = qx * qx + qy * qy + qz * qz;

    int cx, cy, cz;
    cell3(qx, qy, qz, cx, cy, cz);
    int x0 = max(cx - 1, 0), x1 = min(cx + 1, GDIM - 1);
    int y0 = max(cy - 1, 0), y1 = min(cy + 1, GDIM - 1);
    int z0 = max(cz - 1, 0), z1 = min(cz + 1, GDIM - 1);
    int xw = x1 - x0 + 1;

    const int*    Astart = g_Astart + b * NCELL1;
    const float4* As     = g_As + (size_t)b * MAXA;
    const int*    Ai     = g_Ai + (size_t)b * MAXA;

    // Prefetch the (up to 9) contiguous x-run ranges (front-batched LDGs)
    int rp0[9], rp1[9];
    int nr = 0;
    #pragma unroll 1
    for (int z = z0; z <= z1; z++) {
        #pragma unroll 1
        for (int y = y0; y <= y1; y++) {
            int c = (z * GDIM + y) * GDIM + x0;
            rp0[nr] = Astart[c];
            rp1[nr] = Astart[c + xw];
            nr++;
        }
    }

    float dbest = FLT_MAX;
    int ibest = 0;
    #pragma unroll 1
    for (int r = 0; r < nr; r++) {
        int p1 = rp1[r];
        #pragma unroll 1
        for (int p = rp0[r]; p < p1; p++) {
            float4 w = As[p];
            float d = fmaf(w.x, qx, fmaf(w.y, qy, fmaf(w.z, qz, w.w)));
            if (d < dbest) { dbest = d; ibest = Ai[p]; }
            else if (d == dbest) ibest = min(ibest, Ai[p]);
        }
    }

    // Sound certificate: true d2 vs squared distance to scanned-box faces.
    // Grid-edge faces -> infinity (also covers clamped outliers).
    float dlx = (x0 == 0)        ? FLT_MAX : qx - (GX0 + x0 * CH);
    float dhx = (x1 == GDIM - 1) ? FLT_MAX : (GX0 + (x1 + 1) * CH) - qx;
    float dly = (y0 == 0)        ? FLT_MAX : qy - (GX0 + y0 * CH);
    float dhy = (y1 == GDIM - 1) ? FLT_MAX : (GX0 + (y1 + 1) * CH) - qy;
    float dlz = (z0 == 0)        ? FLT_MAX : qz - (GX0 + z0 * CH);
    float dhz = (z1 == GDIM - 1) ? FLT_MAX : (GX0 + (z1 + 1) * CH) - qz;
    float dface = fminf(fminf(fminf(dlx, dhx), fminf(dly, dhy)),
                        fminf(dlz, dhz));
    bool done = valid && (dbest + q2 + MARGIN <= dface * dface);

    int coll = 0;
    if (done) {
        const float* ap = anchor + ((size_t)b * Na + ibest) * 3;
        float dx = qx - ap[0];
        float dy = qy - ap[1];
        float dz = qz - ap[2];
        const float* npx = g_acc + ((size_t)b * MAXA + ibest) * 3;
        float dot = dx * npx[0] + dy * npx[1] + dz * npx[2];
        float l2  = sqrtf(dx * dx + dy * dy + dz * dz);
        coll = ((l2 <= 5.0f) && (dot < 0.0f)) ? 1 : 0;
    } else if (valid) {
        int idx = atomicAdd(&g_fbcnt[b], 1);
        g_fb[b * MAXQ + idx] = s;
    }

    unsigned m = __ballot_sync(0xFFFFFFFFu, coll);
    if ((threadIdx.x & 31) == 0 && m)
        atomicAdd(&out[b], (float)__popc(m));
}

// ---------------------------------------------------------------------------
// K5: exact brute-force fallback: one warp per uncertified query
// ---------------------------------------------------------------------------
__global__ void __launch_bounds__(128)
fallback_kernel(const float* __restrict__ anchor, float* __restrict__ out,
                int Nq, int Na)
{
    int b = blockIdx.y;
    int lane = threadIdx.x & 31;
    int wid = blockIdx.x * 4 + (threadIdx.x >> 5);
    int nwarps = gridDim.x * 4;

    int cnt = g_fbcnt[b];
    const float4* As = g_As + (size_t)b * MAXA;
    const int*    Ai = g_Ai + (size_t)b * MAXA;

    for (int t = wid; t < cnt; t += nwarps) {
        int s = g_fb[b * MAXQ + t];
        float4 qv = g_Qs[b * MAXQ + s];
        float qx = qv.x, qy = qv.y, qz = qv.z;

        u64 kbest = 0xFFFFFFFFFFFFFFFFull;
        for (int p = lane; p < Na; p += 32) {
            float4 w = As[p];
            float d = fmaf(w.x, qx, fmaf(w.y, qy, fmaf(w.z, qz, w.w)));
            u64 key = ((u64)fkey(d) << 32) | (unsigned)Ai[p];
            if (key < kbest) kbest = key;
        }
        #pragma unroll
        for (int o = 16; o >= 1; o >>= 1)
            kbest = min(kbest, __shfl_xor_sync(0xFFFFFFFFu, kbest, o));

        if (lane == 0) {
            int best = (int)(unsigned)(kbest & 0xFFFFFFFFull);
            const float* ap = anchor + ((size_t)b * Na + best) * 3;
            float dx = qx - ap[0];
            float dy = qy - ap[1];
            float dz = qz - ap[2];
            const float* npx = g_acc + ((size_t)b * MAXA + best) * 3;
            float dot = dx * npx[0] + dy * npx[1] + dz * npx[2];
            float l2  = sqrtf(dx * dx + dy * dy + dz * dz);
            if ((l2 <= 5.0f) && (dot < 0.0f))
                atomicAdd(&out[b], 1.0f);
        }
    }
}

// ---------------------------------------------------------------------------
extern "C" void kernel_launch(void* const* d_in, const int* in_sizes, int n_in,
                              void* d_out, int out_size)
{
    const float* query  = (const float*)d_in[0];
    const float* anchor = (const float*)d_in[1];
    const int*   faces  = (const int*)d_in[2];
    float* out = (float*)d_out;

    int Nq = in_sizes[0] / (NB * 3);
    int Na = in_sizes[1] / (NB * 3);
    int F  = in_sizes[2] / 3;

    int zn = NB * NCELL;
    if (NB * MAXA * 3 > zn) zn = NB * MAXA * 3;
    zero_kernel<<<(zn + 255) / 256, 256>>>(out);

    int cn = NB * (Na + Nq + F);
    count_face_kernel<<<(cn + 255) / 256, 256>>>(anchor, query, faces,
                                                 Na, Nq, F);

    scan_kernel<<<8, 1024>>>();

    int sn = NB * (Na + Nq);
    scatter_kernel<<<(sn + 255) / 256, 256>>>(anchor, query, Na, Nq);

    dim3 ngrid((Nq + 127) / 128, NB);
    nn_kernel<<<ngrid, 128>>>(anchor, out, Nq, Na);

    dim3 fgrid(32, NB);
    fallback_kernel<<<fgrid, 128>>>(anchor, out, Nq, Na);
}

// round 9
// speedup vs baseline: 11.8263x; 1.0788x over previous
#include <cuda_runtime.h>
#include <cuda_bf16.h>
#include <float.h>

// B=4. Per query: argmin over anchors of d' = a2 - 2*q.a (same argmin as
// squared distance; first-index tie-break preserved), then count
// dot(diff, summed face normal) < 0 within MAX_DIST. Normal normalization is
// a positive scaling -> sign unchanged -> raw summed face normals suffice.
//
// NN: anchors counting-sorted by row-major 32^3 cell (contiguous x-runs);
// queries counting-sorted by MORTON cell code (warp spatial coherence).
// Per lane: scan nearest 2x2x2 cell box, certify vs box faces; escalate to
// 3x3x3 box on failure; residual (~1%) resolved by exact warp-per-query
// brute force. Every path exact (superset scan + sound face certificates).

#define NB      4
#define GDIM    32
#define NCELL   (GDIM * GDIM * GDIM)
#define NCELL1  (NCELL + 1)
#define MAXA    8192
#define MAXQ    16384
#define GX0     (-5.0f)
#define CH      0.3125f
#define INVH    3.2f
#define MARGIN  1e-3f

typedef unsigned long long u64;

__device__ int    g_Acnt[NB * NCELL];
__device__ int    g_Qcnt[NB * NCELL];
__device__ int    g_Astart[NB * NCELL1];
__device__ int    g_Acur[NB * NCELL];
__device__ int    g_Qstart[NB * NCELL1];
__device__ int    g_Qcur[NB * NCELL];
__device__ float4 g_As[NB * MAXA];   // sorted anchors: (wx,wy,wz,ww)=(-2a,a2)
__device__ int    g_Ai[NB * MAXA];   // sorted slot -> original anchor idx
__device__ float4 g_Qs[NB * MAXQ];   // Morton-sorted queries (x,y,z,0)
__device__ float  g_acc[NB * MAXA * 3];
__device__ int    g_fbcnt[NB];
__device__ int    g_fb[NB * MAXQ];

__device__ __forceinline__ int clampi(int v, int lo, int hi) {
    return v < lo ? lo : (v > hi ? hi : v);
}
__device__ __forceinline__ void cell3(float x, float y, float z,
                                      int& cx, int& cy, int& cz) {
    cx = clampi(__float2int_rd((x - GX0) * INVH), 0, GDIM - 1);
    cy = clampi(__float2int_rd((y - GX0) * INVH), 0, GDIM - 1);
    cz = clampi(__float2int_rd((z - GX0) * INVH), 0, GDIM - 1);
}
__device__ __forceinline__ int cell_row(float x, float y, float z) {
    int cx, cy, cz;
    cell3(x, y, z, cx, cy, cz);
    return (cz * GDIM + cy) * GDIM + cx;
}
__device__ __forceinline__ int morton5(int x, int y, int z) {
    int m = 0;
    #pragma unroll
    for (int i = 0; i < 5; i++)
        m |= (((x >> i) & 1) << (3 * i)) |
             (((y >> i) & 1) << (3 * i + 1)) |
             (((z >> i) & 1) << (3 * i + 2));
    return m;
}
__device__ __forceinline__ int cell_mort(float x, float y, float z) {
    int cx, cy, cz;
    cell3(x, y, z, cx, cy, cz);
    return morton5(cx, cy, cz);
}
// Monotone float-bits -> u32 key (smaller float -> smaller key). No NaNs.
__device__ __forceinline__ unsigned fkey(float f) {
    unsigned b = __float_as_uint(f);
    return (b & 0x80000000u) ? ~b : (b | 0x80000000u);
}

// Exact scan of a contiguous sorted-anchor run; min distance, min orig idx
// on exact float ties. 2-deep load batching for MLP.
__device__ __forceinline__ void scan_run(const float4* __restrict__ As,
                                         const int* __restrict__ Ai,
                                         int p, int p1,
                                         float qx, float qy, float qz,
                                         float& dbest, int& ibest)
{
    for (; p + 2 <= p1; p += 2) {
        float4 w0 = As[p];
        float4 w1 = As[p + 1];
        float d0 = fmaf(w0.x, qx, fmaf(w0.y, qy, fmaf(w0.z, qz, w0.w)));
        float d1 = fmaf(w1.x, qx, fmaf(w1.y, qy, fmaf(w1.z, qz, w1.w)));
        if (d0 < dbest)       { dbest = d0; ibest = Ai[p]; }
        else if (d0 == dbest) { ibest = min(ibest, Ai[p]); }
        if (d1 < dbest)       { dbest = d1; ibest = Ai[p + 1]; }
        else if (d1 == dbest) { ibest = min(ibest, Ai[p + 1]); }
    }
    if (p < p1) {
        float4 w = As[p];
        float d = fmaf(w.x, qx, fmaf(w.y, qy, fmaf(w.z, qz, w.w)));
        if (d < dbest)       { dbest = d; ibest = Ai[p]; }
        else if (d == dbest) { ibest = min(ibest, Ai[p]); }
    }
}

// ---------------------------------------------------------------------------
// K0: zero counters / accumulators / output / fallback counts
// ---------------------------------------------------------------------------
__global__ void zero_kernel(float* __restrict__ out)
{
    int i = blockIdx.x * blockDim.x + threadIdx.x;
    if (i < NB) { out[i] = 0.0f; g_fbcnt[i] = 0; }
    if (i < NB * NCELL) { g_Acnt[i] = 0; g_Qcnt[i] = 0; }
    if (i < NB * MAXA * 3) g_acc[i] = 0.0f;
}

// ---------------------------------------------------------------------------
// K1: fused per-cell counting (anchors row-major, queries Morton) + faces
// ---------------------------------------------------------------------------
__global__ void count_face_kernel(const float* __restrict__ anchor,
                                  const float* __restrict__ query,
                                  const int* __restrict__ faces,
                                  int Na, int Nq, int F)
{
    int i = blockIdx.x * blockDim.x + threadIdx.x;
    int totA = NB * Na;
    if (i < totA) {
        int b = i / Na;
        int c = cell_row(anchor[3 * i], anchor[3 * i + 1], anchor[3 * i + 2]);
        atomicAdd(&g_Acnt[b * NCELL + c], 1);
        return;
    }
    int j = i - totA;
    if (j < NB * Nq) {
        int b = j / Nq;
        int c = cell_mort(query[3 * j], query[3 * j + 1], query[3 * j + 2]);
        atomicAdd(&g_Qcnt[b * NCELL + c], 1);
        return;
    }
    int k = j - NB * Nq;
    if (k >= NB * F) return;
    int b = k / F;
    int f = k - b * F;

    int i0 = faces[3 * f + 0];
    int i1 = faces[3 * f + 1];
    int i2 = faces[3 * f + 2];

    const float* base = anchor + (size_t)b * Na * 3;
    float v0x = base[3 * i0 + 0], v0y = base[3 * i0 + 1], v0z = base[3 * i0 + 2];
    float v1x = base[3 * i1 + 0], v1y = base[3 * i1 + 1], v1z = base[3 * i1 + 2];
    float v2x = base[3 * i2 + 0], v2y = base[3 * i2 + 1], v2z = base[3 * i2 + 2];

    float e1x = v1x - v0x, e1y = v1y - v0y, e1z = v1z - v0z;
    float e2x = v2x - v0x, e2y = v2y - v0y, e2z = v2z - v0z;

    float nx = e1y * e2z - e1z * e2y;
    float ny = e1z * e2x - e1x * e2z;
    float nz = e1x * e2y - e1y * e2x;

    float* acc = g_acc + (size_t)b * MAXA * 3;
    atomicAdd(&acc[3 * i0 + 0], nx);
    atomicAdd(&acc[3 * i0 + 1], ny);
    atomicAdd(&acc[3 * i0 + 2], nz);
    atomicAdd(&acc[3 * i1 + 0], nx);
    atomicAdd(&acc[3 * i1 + 1], ny);
    atomicAdd(&acc[3 * i1 + 2], nz);
    atomicAdd(&acc[3 * i2 + 0], nx);
    atomicAdd(&acc[3 * i2 + 1], ny);
    atomicAdd(&acc[3 * i2 + 2], nz);
}

// ---------------------------------------------------------------------------
// K2: exclusive scan of 32768 counts per (batch, kind). 8 blocks x 1024 thr.
// ---------------------------------------------------------------------------
__global__ void __launch_bounds__(1024)
scan_kernel()
{
    __shared__ int sp[1024];
    int which = blockIdx.x;            // 0..3 anchors, 4..7 queries
    int b = which & 3;
    bool isQ = which >= 4;
    const int* cnt = (isQ ? g_Qcnt : g_Acnt) + b * NCELL;
    int* start = (isQ ? g_Qstart : g_Astart) + b * NCELL1;
    int* cur   = (isQ ? g_Qcur   : g_Acur)   + b * NCELL;

    int t = threadIdx.x;
    int c0 = t * 32;
    int loc[32];
    int s = 0;
    #pragma unroll
    for (int i = 0; i < 32; i++) { loc[i] = s; s += cnt[c0 + i]; }
    sp[t] = s;
    __syncthreads();
    for (int off = 1; off < 1024; off <<= 1) {
        int v = (t >= off) ? sp[t - off] : 0;
        __syncthreads();
        sp[t] += v;
        __syncthreads();
    }
    int base = sp[t] - s;
    #pragma unroll
    for (int i = 0; i < 32; i++) {
        int v = base + loc[i];
        start[c0 + i] = v;
        cur[c0 + i] = v;
    }
    if (t == 1023) start[NCELL] = sp[1023];
}

// ---------------------------------------------------------------------------
// K3: scatter anchors (row-major cells) and queries (Morton) into order
// ---------------------------------------------------------------------------
__global__ void scatter_kernel(const float* __restrict__ anchor,
                               const float* __restrict__ query,
                               int Na, int Nq)
{
    int i = blockIdx.x * blockDim.x + threadIdx.x;
    int totA = NB * Na;
    if (i < totA) {
        int b = i / Na;
        int a = i - b * Na;
        float x = anchor[3 * i], y = anchor[3 * i + 1], z = anchor[3 * i + 2];
        int c = cell_row(x, y, z);
        int pos = atomicAdd(&g_Acur[b * NCELL + c], 1);
        g_As[b * MAXA + pos] = make_float4(-2.0f * x, -2.0f * y, -2.0f * z,
                                           x * x + y * y + z * z);
        g_Ai[b * MAXA + pos] = a;
        return;
    }
    int j = i - totA;
    if (j >= NB * Nq) return;
    int b = j / Nq;
    float x = query[3 * j], y = query[3 * j + 1], z = query[3 * j + 2];
    int c = cell_mort(x, y, z);
    int pos = atomicAdd(&g_Qcur[b * NCELL + c], 1);
    g_Qs[b * MAXQ + pos] = make_float4(x, y, z, 0.0f);
}

// ---------------------------------------------------------------------------
// K4: two-level per-lane NN scan + certificates; fallback push if needed
// ---------------------------------------------------------------------------
__global__ void __launch_bounds__(128)
nn_kernel(const float* __restrict__ anchor, float* __restrict__ out,
          int Nq, int Na)
{
    int b = blockIdx.y;
    int s = blockIdx.x * 128 + threadIdx.x;
    bool valid = (s < Nq);
    int sc = valid ? s : (Nq - 1);

    float4 qv = g_Qs[b * MAXQ + sc];
    float qx = qv.x, qy = qv.y, qz = qv.z;
    float q2 = qx * qx + qy * qy + qz * qz;

    int cx, cy, cz;
    cell3(qx, qy, qz, cx, cy, cz);

    const int*    Astart = g_Astart + b * NCELL1;
    const float4* As     = g_As + (size_t)b * MAXA;
    const int*    Ai     = g_Ai + (size_t)b * MAXA;

    float dbest = FLT_MAX;
    int ibest = 0;
    bool done = false;

    // ---- level 1: nearest 2x2x2 cell box ----
    {
        float fx = (qx - GX0) * INVH - (float)cx;
        float fy = (qy - GX0) * INVH - (float)cy;
        float fz = (qz - GX0) * INVH - (float)cz;
        int bx = clampi((fx < 0.5f) ? cx - 1 : cx, 0, GDIM - 2);
        int by = clampi((fy < 0.5f) ? cy - 1 : cy, 0, GDIM - 2);
        int bz = clampi((fz < 0.5f) ? cz - 1 : cz, 0, GDIM - 2);

        #pragma unroll
        for (int dz = 0; dz < 2; dz++) {
            #pragma unroll
            for (int dy = 0; dy < 2; dy++) {
                int c = ((bz + dz) * GDIM + (by + dy)) * GDIM + bx;
                scan_run(As, Ai, Astart[c], Astart[c + 2],
                         qx, qy, qz, dbest, ibest);
            }
        }

        float dlx = (bx == 0)            ? FLT_MAX : qx - (GX0 + bx * CH);
        float dhx = (bx + 1 == GDIM - 1) ? FLT_MAX : (GX0 + (bx + 2) * CH) - qx;
        float dly = (by == 0)            ? FLT_MAX : qy - (GX0 + by * CH);
        float dhy = (by + 1 == GDIM - 1) ? FLT_MAX : (GX0 + (by + 2) * CH) - qy;
        float dlz = (bz == 0)            ? FLT_MAX : qz - (GX0 + bz * CH);
        float dhz = (bz + 1 == GDIM - 1) ? FLT_MAX : (GX0 + (bz + 2) * CH) - qz;
        float dface = fminf(fminf(fminf(dlx, dhx), fminf(dly, dhy)),
                            fminf(dlz, dhz));
        done = (dbest + q2 + MARGIN <= dface * dface);
    }

    // ---- level 2: 3x3x3 box (superset rescan, still exact) ----
    if (!done) {
        int x0 = max(cx - 1, 0), x1 = min(cx + 1, GDIM - 1);
        int y0 = max(cy - 1, 0), y1 = min(cy + 1, GDIM - 1);
        int z0 = max(cz - 1, 0), z1 = min(cz + 1, GDIM - 1);
        int xw = x1 - x0 + 1;

        #pragma unroll 1
        for (int z = z0; z <= z1; z++) {
            #pragma unroll 1
            for (int y = y0; y <= y1; y++) {
                int c = (z * GDIM + y) * GDIM + x0;
                scan_run(As, Ai, Astart[c], Astart[c + xw],
                         qx, qy, qz, dbest, ibest);
            }
        }

        float dlx = (x0 == 0)        ? FLT_MAX : qx - (GX0 + x0 * CH);
        float dhx = (x1 == GDIM - 1) ? FLT_MAX : (GX0 + (x1 + 1) * CH) - qx;
        float dly = (y0 == 0)        ? FLT_MAX : qy - (GX0 + y0 * CH);
        float dhy = (y1 == GDIM - 1) ? FLT_MAX : (GX0 + (y1 + 1) * CH) - qy;
        float dlz = (z0 == 0)        ? FLT_MAX : qz - (GX0 + z0 * CH);
        float dhz = (z1 == GDIM - 1) ? FLT_MAX : (GX0 + (z1 + 1) * CH) - qz;
        float dface = fminf(fminf(fminf(dlx, dhx), fminf(dly, dhy)),
                            fminf(dlz, dhz));
        done = (dbest + q2 + MARGIN <= dface * dface);
    }

    int coll = 0;
    if (valid && done) {
        const float* ap = anchor + ((size_t)b * Na + ibest) * 3;
        float dx = qx - ap[0];
        float dy = qy - ap[1];
        float dz = qz - ap[2];
        const float* npx = g_acc + ((size_t)b * MAXA + ibest) * 3;
        float dot = dx * npx[0] + dy * npx[1] + dz * npx[2];
        float l2  = sqrtf(dx * dx + dy * dy + dz * dz);
        coll = ((l2 <= 5.0f) && (dot < 0.0f)) ? 1 : 0;
    } else if (valid) {
        int idx = atomicAdd(&g_fbcnt[b], 1);
        g_fb[b * MAXQ + idx] = s;
    }

    unsigned m = __ballot_sync(0xFFFFFFFFu, coll);
    if ((threadIdx.x & 31) == 0 && m)
        atomicAdd(&out[b], (float)__popc(m));
}

// ---------------------------------------------------------------------------
// K5: exact brute-force fallback: one warp per uncertified query
// ---------------------------------------------------------------------------
__global__ void __launch_bounds__(128)
fallback_kernel(const float* __restrict__ anchor, float* __restrict__ out,
                int Nq, int Na)
{
    int b = blockIdx.y;
    int lane = threadIdx.x & 31;
    int wid = blockIdx.x * 4 + (threadIdx.x >> 5);
    int nwarps = gridDim.x * 4;

    int cnt = g_fbcnt[b];
    const float4* As = g_As + (size_t)b * MAXA;
    const int*    Ai = g_Ai + (size_t)b * MAXA;

    for (int t = wid; t < cnt; t += nwarps) {
        int s = g_fb[b * MAXQ + t];
        float4 qv = g_Qs[b * MAXQ + s];
        float qx = qv.x, qy = qv.y, qz = qv.z;

        u64 kbest = 0xFFFFFFFFFFFFFFFFull;
        for (int p = lane; p < Na; p += 32) {
            float4 w = As[p];
            float d = fmaf(w.x, qx, fmaf(w.y, qy, fmaf(w.z, qz, w.w)));
            u64 key = ((u64)fkey(d) << 32) | (unsigned)Ai[p];
            if (key < kbest) kbest = key;
        }
        #pragma unroll
        for (int o = 16; o >= 1; o >>= 1)
            kbest = min(kbest, __shfl_xor_sync(0xFFFFFFFFu, kbest, o));

        if (lane == 0) {
            int best = (int)(unsigned)(kbest & 0xFFFFFFFFull);
            const float* ap = anchor + ((size_t)b * Na + best) * 3;
            float dx = qx - ap[0];
            float dy = qy - ap[1];
            float dz = qz - ap[2];
            const float* npx = g_acc + ((size_t)b * MAXA + best) * 3;
            float dot = dx * npx[0] + dy * npx[1] + dz * npx[2];
            float l2  = sqrtf(dx * dx + dy * dy + dz * dz);
            if ((l2 <= 5.0f) && (dot < 0.0f))
                atomicAdd(&out[b], 1.0f);
        }
    }
}

// ---------------------------------------------------------------------------
extern "C" void kernel_launch(void* const* d_in, const int* in_sizes, int n_in,
                              void* d_out, int out_size)
{
    const float* query  = (const float*)d_in[0];
    const float* anchor = (const float*)d_in[1];
    const int*   faces  = (const int*)d_in[2];
    float* out = (float*)d_out;

    int Nq = in_sizes[0] / (NB * 3);
    int Na = in_sizes[1] / (NB * 3);
    int F  = in_sizes[2] / 3;

    int zn = NB * NCELL;
    if (NB * MAXA * 3 > zn) zn = NB * MAXA * 3;
    zero_kernel<<<(zn + 255) / 256, 256>>>(out);

    int cn = NB * (Na + Nq + F);
    count_face_kernel<<<(cn + 255) / 256, 256>>>(anchor, query, faces,
                                                 Na, Nq, F);

    scan_kernel<<<8, 1024>>>();

    int sn = NB * (Na + Nq);
    scatter_kernel<<<(sn + 255) / 256, 256>>>(anchor, query, Na, Nq);

    dim3 ngrid((Nq + 127) / 128, NB);
    nn_kernel<<<ngrid, 128>>>(anchor, out, Nq, Na);

    dim3 fgrid(32, NB);
    fallback_kernel<<<fgrid, 128>>>(anchor, out, Nq, Na);
}

// round 11
// speedup vs baseline: 13.3155x; 1.1259x over previous
#include <cuda_runtime.h>
#include <cuda_bf16.h>
#include <float.h>

// B=4. Per query: argmin over anchors of d' = a2 - 2*q.a (same argmin as
// squared distance; first-index tie-break preserved), then count
// dot(diff, summed face normal) < 0 within MAX_DIST. Normal normalization is
// a positive scaling -> sign unchanged -> raw summed face normals suffice.
//
// NN: anchors counting-sorted by row-major 32^3 cell (contiguous x-runs);
// queries counting-sorted by MORTON code (warp coherence). FOUR threads per
// query: level-1 2x2x2 box = 4 x-runs, one per sub-lane; level-2 3x3x3 box
// runs split r=sub,sub+4,...; merge via shfl_xor on (fkey<<32|idx) keys.
// Level-2 entered at WARP scope (any_sync) so shfl merges stay convergent.
// Sound face certificates; residual queries resolved by exact warp-per-query
// brute force. Every path exact.

#define NB      4
#define GDIM    32
#define NCELL   (GDIM * GDIM * GDIM)
#define NCELL1  (NCELL + 1)
#define MAXA    8192
#define MAXQ    16384
#define GX0     (-5.0f)
#define CH      0.3125f
#define INVH    3.2f
#define MARGIN  1e-3f

typedef unsigned long long u64;

__device__ int    g_Acnt[NB * NCELL];
__device__ int    g_Qcnt[NB * NCELL];
__device__ int    g_Astart[NB * NCELL1];
__device__ int    g_Acur[NB * NCELL];
__device__ int    g_Qstart[NB * NCELL1];
__device__ int    g_Qcur[NB * NCELL];
__device__ float4 g_As[NB * MAXA];   // sorted anchors: (wx,wy,wz,ww)=(-2a,a2)
__device__ int    g_Ai[NB * MAXA];   // sorted slot -> original anchor idx
__device__ float4 g_Qs[NB * MAXQ];   // Morton-sorted queries (x,y,z,0)
__device__ float  g_acc[NB * MAXA * 3];
__device__ int    g_fbcnt[NB];
__device__ int    g_fb[NB * MAXQ];

__device__ __forceinline__ int clampi(int v, int lo, int hi) {
    return v < lo ? lo : (v > hi ? hi : v);
}
__device__ __forceinline__ void cell3(float x, float y, float z,
                                      int& cx, int& cy, int& cz) {
    cx = clampi(__float2int_rd((x - GX0) * INVH), 0, GDIM - 1);
    cy = clampi(__float2int_rd((y - GX0) * INVH), 0, GDIM - 1);
    cz = clampi(__float2int_rd((z - GX0) * INVH), 0, GDIM - 1);
}
__device__ __forceinline__ int cell_row(float x, float y, float z) {
    int cx, cy, cz;
    cell3(x, y, z, cx, cy, cz);
    return (cz * GDIM + cy) * GDIM + cx;
}
__device__ __forceinline__ int morton5(int x, int y, int z) {
    int m = 0;
    #pragma unroll
    for (int i = 0; i < 5; i++)
        m |= (((x >> i) & 1) << (3 * i)) |
             (((y >> i) & 1) << (3 * i + 1)) |
             (((z >> i) & 1) << (3 * i + 2));
    return m;
}
__device__ __forceinline__ int cell_mort(float x, float y, float z) {
    int cx, cy, cz;
    cell3(x, y, z, cx, cy, cz);
    return morton5(cx, cy, cz);
}
// Monotone float-bits -> u32 key (smaller float -> smaller key). No NaNs.
__device__ __forceinline__ unsigned fkey(float f) {
    unsigned b = __float_as_uint(f);
    return (b & 0x80000000u) ? ~b : (b | 0x80000000u);
}

// Exact scan of a contiguous sorted-anchor run, accumulating min key
// (fkey(d)<<32 | orig_idx): smaller distance wins, ties -> smaller orig idx.
__device__ __forceinline__ void scan_run_key(const float4* __restrict__ As,
                                             const int* __restrict__ Ai,
                                             int p, int p1,
                                             float qx, float qy, float qz,
                                             u64& kbest)
{
    for (; p + 2 <= p1; p += 2) {
        float4 w0 = As[p];
        float4 w1 = As[p + 1];
        int a0 = Ai[p];
        int a1 = Ai[p + 1];
        float d0 = fmaf(w0.x, qx, fmaf(w0.y, qy, fmaf(w0.z, qz, w0.w)));
        float d1 = fmaf(w1.x, qx, fmaf(w1.y, qy, fmaf(w1.z, qz, w1.w)));
        u64 k0 = ((u64)fkey(d0) << 32) | (unsigned)a0;
        u64 k1 = ((u64)fkey(d1) << 32) | (unsigned)a1;
        if (k0 < kbest) kbest = k0;
        if (k1 < kbest) kbest = k1;
    }
    if (p < p1) {
        float4 w = As[p];
        int a0 = Ai[p];
        float d = fmaf(w.x, qx, fmaf(w.y, qy, fmaf(w.z, qz, w.w)));
        u64 k = ((u64)fkey(d) << 32) | (unsigned)a0;
        if (k < kbest) kbest = k;
    }
}
__device__ __forceinline__ float key2dist(u64 k) {
    unsigned kb = (unsigned)(k >> 32);
    unsigned b = (kb & 0x80000000u) ? (kb & 0x7FFFFFFFu) : ~kb;
    return __uint_as_float(b);
}

// ---------------------------------------------------------------------------
// K0: zero counters / accumulators / output / fallback counts
// ---------------------------------------------------------------------------
__global__ void zero_kernel(float* __restrict__ out)
{
    int i = blockIdx.x * blockDim.x + threadIdx.x;
    if (i < NB) { out[i] = 0.0f; g_fbcnt[i] = 0; }
    if (i < NB * NCELL) { g_Acnt[i] = 0; g_Qcnt[i] = 0; }
    if (i < NB * MAXA * 3) g_acc[i] = 0.0f;
}

// ---------------------------------------------------------------------------
// K1: fused per-cell counting (anchors row-major, queries Morton) + faces
// ---------------------------------------------------------------------------
__global__ void count_face_kernel(const float* __restrict__ anchor,
                                  const float* __restrict__ query,
                                  const int* __restrict__ faces,
                                  int Na, int Nq, int F)
{
    int i = blockIdx.x * blockDim.x + threadIdx.x;
    int totA = NB * Na;
    if (i < totA) {
        int b = i / Na;
        int c = cell_row(anchor[3 * i], anchor[3 * i + 1], anchor[3 * i + 2]);
        atomicAdd(&g_Acnt[b * NCELL + c], 1);
        return;
    }
    int j = i - totA;
    if (j < NB * Nq) {
        int b = j / Nq;
        int c = cell_mort(query[3 * j], query[3 * j + 1], query[3 * j + 2]);
        atomicAdd(&g_Qcnt[b * NCELL + c], 1);
        return;
    }
    int k = j - NB * Nq;
    if (k >= NB * F) return;
    int b = k / F;
    int f = k - b * F;

    int i0 = faces[3 * f + 0];
    int i1 = faces[3 * f + 1];
    int i2 = faces[3 * f + 2];

    const float* base = anchor + (size_t)b * Na * 3;
    float v0x = base[3 * i0 + 0], v0y = base[3 * i0 + 1], v0z = base[3 * i0 + 2];
    float v1x = base[3 * i1 + 0], v1y = base[3 * i1 + 1], v1z = base[3 * i1 + 2];
    float v2x = base[3 * i2 + 0], v2y = base[3 * i2 + 1], v2z = base[3 * i2 + 2];

    float e1x = v1x - v0x, e1y = v1y - v0y, e1z = v1z - v0z;
    float e2x = v2x - v0x, e2y = v2y - v0y, e2z = v2z - v0z;

    float nx = e1y * e2z - e1z * e2y;
    float ny = e1z * e2x - e1x * e2z;
    float nz = e1x * e2y - e1y * e2x;

    float* acc = g_acc + (size_t)b * MAXA * 3;
    atomicAdd(&acc[3 * i0 + 0], nx);
    atomicAdd(&acc[3 * i0 + 1], ny);
    atomicAdd(&acc[3 * i0 + 2], nz);
    atomicAdd(&acc[3 * i1 + 0], nx);
    atomicAdd(&acc[3 * i1 + 1], ny);
    atomicAdd(&acc[3 * i1 + 2], nz);
    atomicAdd(&acc[3 * i2 + 0], nx);
    atomicAdd(&acc[3 * i2 + 1], ny);
    atomicAdd(&acc[3 * i2 + 2], nz);
}

// ---------------------------------------------------------------------------
// K2: exclusive scan of 32768 counts per (batch, kind). 8 blocks x 1024 thr.
// ---------------------------------------------------------------------------
__global__ void __launch_bounds__(1024)
scan_kernel()
{
    __shared__ int sp[1024];
    int which = blockIdx.x;            // 0..3 anchors, 4..7 queries
    int b = which & 3;
    bool isQ = which >= 4;
    const int* cnt = (isQ ? g_Qcnt : g_Acnt) + b * NCELL;
    int* start = (isQ ? g_Qstart : g_Astart) + b * NCELL1;
    int* cur   = (isQ ? g_Qcur   : g_Acur)   + b * NCELL;

    int t = threadIdx.x;
    int c0 = t * 32;
    int loc[32];
    int s = 0;
    #pragma unroll
    for (int i = 0; i < 32; i++) { loc[i] = s; s += cnt[c0 + i]; }
    sp[t] = s;
    __syncthreads();
    for (int off = 1; off < 1024; off <<= 1) {
        int v = (t >= off) ? sp[t - off] : 0;
        __syncthreads();
        sp[t] += v;
        __syncthreads();
    }
    int base = sp[t] - s;
    #pragma unroll
    for (int i = 0; i < 32; i++) {
        int v = base + loc[i];
        start[c0 + i] = v;
        cur[c0 + i] = v;
    }
    if (t == 1023) start[NCELL] = sp[1023];
}

// ---------------------------------------------------------------------------
// K3: scatter anchors (row-major cells) and queries (Morton) into order
// ---------------------------------------------------------------------------
__global__ void scatter_kernel(const float* __restrict__ anchor,
                               const float* __restrict__ query,
                               int Na, int Nq)
{
    int i = blockIdx.x * blockDim.x + threadIdx.x;
    int totA = NB * Na;
    if (i < totA) {
        int b = i / Na;
        int a = i - b * Na;
        float x = anchor[3 * i], y = anchor[3 * i + 1], z = anchor[3 * i + 2];
        int c = cell_row(x, y, z);
        int pos = atomicAdd(&g_Acur[b * NCELL + c], 1);
        g_As[b * MAXA + pos] = make_float4(-2.0f * x, -2.0f * y, -2.0f * z,
                                           x * x + y * y + z * z);
        g_Ai[b * MAXA + pos] = a;
        return;
    }
    int j = i - totA;
    if (j >= NB * Nq) return;
    int b = j / Nq;
    float x = query[3 * j], y = query[3 * j + 1], z = query[3 * j + 2];
    int c = cell_mort(x, y, z);
    int pos = atomicAdd(&g_Qcur[b * NCELL + c], 1);
    g_Qs[b * MAXQ + pos] = make_float4(x, y, z, 0.0f);
}

// ---------------------------------------------------------------------------
// K4: 4-threads-per-query two-level NN + certificates; fallback if needed.
// All shfl merges execute at warp scope (convergent).
// ---------------------------------------------------------------------------
__global__ void __launch_bounds__(256)
nn_kernel(const float* __restrict__ anchor, float* __restrict__ out,
          int Nq, int Na)
{
    int b = blockIdx.y;
    int t = blockIdx.x * 256 + threadIdx.x;
    int s = t >> 2;            // query (sorted slot)
    int sub = t & 3;           // sub-lane within query group
    bool valid = (s < Nq);
    int sc = valid ? s : (Nq - 1);

    float4 qv = g_Qs[b * MAXQ + sc];
    float qx = qv.x, qy = qv.y, qz = qv.z;
    float q2 = qx * qx + qy * qy + qz * qz;

    int cx, cy, cz;
    cell3(qx, qy, qz, cx, cy, cz);

    const int*    Astart = g_Astart + b * NCELL1;
    const float4* As     = g_As + (size_t)b * MAXA;
    const int*    Ai     = g_Ai + (size_t)b * MAXA;

    u64 kbest = 0xFFFFFFFFFFFFFFFFull;

    // ---- level 1: 2x2x2 box; run 'sub' of 4 (dz = sub>>1, dy = sub&1) ----
    float fx = (qx - GX0) * INVH - (float)cx;
    float fy = (qy - GX0) * INVH - (float)cy;
    float fz = (qz - GX0) * INVH - (float)cz;
    int bx = clampi((fx < 0.5f) ? cx - 1 : cx, 0, GDIM - 2);
    int by = clampi((fy < 0.5f) ? cy - 1 : cy, 0, GDIM - 2);
    int bz = clampi((fz < 0.5f) ? cz - 1 : cz, 0, GDIM - 2);

    {
        int c = ((bz + (sub >> 1)) * GDIM + (by + (sub & 1))) * GDIM + bx;
        scan_run_key(As, Ai, Astart[c], Astart[c + 2], qx, qy, qz, kbest);
    }

    // merge across the 4 sub-lanes (warp-scope, convergent)
    kbest = min(kbest, __shfl_xor_sync(0xFFFFFFFFu, kbest, 1));
    kbest = min(kbest, __shfl_xor_sync(0xFFFFFFFFu, kbest, 2));
    float dbest = key2dist(kbest);

    float dlx = (bx == 0)            ? FLT_MAX : qx - (GX0 + bx * CH);
    float dhx = (bx + 1 == GDIM - 1) ? FLT_MAX : (GX0 + (bx + 2) * CH) - qx;
    float dly = (by == 0)            ? FLT_MAX : qy - (GX0 + by * CH);
    float dhy = (by + 1 == GDIM - 1) ? FLT_MAX : (GX0 + (by + 2) * CH) - qy;
    float dlz = (bz == 0)            ? FLT_MAX : qz - (GX0 + bz * CH);
    float dhz = (bz + 1 == GDIM - 1) ? FLT_MAX : (GX0 + (bz + 2) * CH) - qz;
    float dface = fminf(fminf(fminf(dlx, dhx), fminf(dly, dhy)),
                        fminf(dlz, dhz));
    bool done = (dbest + q2 + MARGIN <= dface * dface);

    // ---- level 2: 3x3x3 box; entered at WARP scope; done lanes skip scans
    if (__any_sync(0xFFFFFFFFu, !done)) {
        int x0 = max(cx - 1, 0), x1 = min(cx + 1, GDIM - 1);
        int y0 = max(cy - 1, 0), y1 = min(cy + 1, GDIM - 1);
        int z0 = max(cz - 1, 0), z1 = min(cz + 1, GDIM - 1);
        int xw = x1 - x0 + 1;
        int yw = y1 - y0 + 1;
        int zw = z1 - z0 + 1;
        int nruns = yw * zw;

        if (!done) {              // no sync inside: divergence here is safe
            #pragma unroll 1
            for (int r = sub; r < nruns; r += 4) {
                int z = z0 + r / yw;
                int y = y0 + r % yw;
                int c = (z * GDIM + y) * GDIM + x0;
                scan_run_key(As, Ai, Astart[c], Astart[c + xw],
                             qx, qy, qz, kbest);
            }
        }

        // warp-scope merges (idempotent for already-done groups)
        kbest = min(kbest, __shfl_xor_sync(0xFFFFFFFFu, kbest, 1));
        kbest = min(kbest, __shfl_xor_sync(0xFFFFFFFFu, kbest, 2));

        if (!done) {
            dbest = key2dist(kbest);
            float elx = (x0 == 0)        ? FLT_MAX : qx - (GX0 + x0 * CH);
            float ehx = (x1 == GDIM - 1) ? FLT_MAX : (GX0 + (x1 + 1) * CH) - qx;
            float ely = (y0 == 0)        ? FLT_MAX : qy - (GX0 + y0 * CH);
            float ehy = (y1 == GDIM - 1) ? FLT_MAX : (GX0 + (y1 + 1) * CH) - qy;
            float elz = (z0 == 0)        ? FLT_MAX : qz - (GX0 + z0 * CH);
            float ehz = (z1 == GDIM - 1) ? FLT_MAX : (GX0 + (z1 + 1) * CH) - qz;
            float dface2 = fminf(fminf(fminf(elx, ehx), fminf(ely, ehy)),
                                 fminf(elz, ehz));
            done = (dbest + q2 + MARGIN <= dface2 * dface2);
        }
    }

    int coll = 0;
    if (valid && sub == 0) {
        if (done) {
            int ibest = (int)(unsigned)(kbest & 0xFFFFFFFFull);
            const float* ap = anchor + ((size_t)b * Na + ibest) * 3;
            float dx = qx - ap[0];
            float dy = qy - ap[1];
            float dz = qz - ap[2];
            const float* npx = g_acc + ((size_t)b * MAXA + ibest) * 3;
            float dot = dx * npx[0] + dy * npx[1] + dz * npx[2];
            float l2  = sqrtf(dx * dx + dy * dy + dz * dz);
            coll = ((l2 <= 5.0f) && (dot < 0.0f)) ? 1 : 0;
        } else {
            int idx = atomicAdd(&g_fbcnt[b], 1);
            g_fb[b * MAXQ + idx] = s;
        }
    }

    unsigned m = __ballot_sync(0xFFFFFFFFu, coll);
    if ((threadIdx.x & 31) == 0 && m)
        atomicAdd(&out[b], (float)__popc(m));
}

// ---------------------------------------------------------------------------
// K5: exact brute-force fallback: one warp per uncertified query
// ---------------------------------------------------------------------------
__global__ void __launch_bounds__(128)
fallback_kernel(const float* __restrict__ anchor, float* __restrict__ out,
                int Nq, int Na)
{
    int b = blockIdx.y;
    int lane = threadIdx.x & 31;
    int wid = blockIdx.x * 4 + (threadIdx.x >> 5);
    int nwarps = gridDim.x * 4;

    int cnt = g_fbcnt[b];
    const float4* As = g_As + (size_t)b * MAXA;
    const int*    Ai = g_Ai + (size_t)b * MAXA;

    for (int t = wid; t < cnt; t += nwarps) {
        int s = g_fb[b * MAXQ + t];
        float4 qv = g_Qs[b * MAXQ + s];
        float qx = qv.x, qy = qv.y, qz = qv.z;

        u64 kbest = 0xFFFFFFFFFFFFFFFFull;
        for (int p = lane; p < Na; p += 32) {
            float4 w = As[p];
            float d = fmaf(w.x, qx, fmaf(w.y, qy, fmaf(w.z, qz, w.w)));
            u64 key = ((u64)fkey(d) << 32) | (unsigned)Ai[p];
            if (key < kbest) kbest = key;
        }
        #pragma unroll
        for (int o = 16; o >= 1; o >>= 1)
            kbest = min(kbest, __shfl_xor_sync(0xFFFFFFFFu, kbest, o));

        if (lane == 0) {
            int best = (int)(unsigned)(kbest & 0xFFFFFFFFull);
            const float* ap = anchor + ((size_t)b * Na + best) * 3;
            float dx = qx - ap[0];
            float dy = qy - ap[1];
            float dz = qz - ap[2];
            const float* npx = g_acc + ((size_t)b * MAXA + best) * 3;
            float dot = dx * npx[0] + dy * npx[1] + dz * npx[2];
            float l2  = sqrtf(dx * dx + dy * dy + dz * dz);
            if ((l2 <= 5.0f) && (dot < 0.0f))
                atomicAdd(&out[b], 1.0f);
        }
    }
}

// ---------------------------------------------------------------------------
extern "C" void kernel_launch(void* const* d_in, const int* in_sizes, int n_in,
                              void* d_out, int out_size)
{
    const float* query  = (const float*)d_in[0];
    const float* anchor = (const float*)d_in[1];
    const int*   faces  = (const int*)d_in[2];
    float* out = (float*)d_out;

    int Nq = in_sizes[0] / (NB * 3);
    int Na = in_sizes[1] / (NB * 3);
    int F  = in_sizes[2] / 3;

    int zn = NB * NCELL;
    if (NB * MAXA * 3 > zn) zn = NB * MAXA * 3;
    zero_kernel<<<(zn + 255) / 256, 256>>>(out);

    int cn = NB * (Na + Nq + F);
    count_face_kernel<<<(cn + 255) / 256, 256>>>(anchor, query, faces,
                                                 Na, Nq, F);

    scan_kernel<<<8, 1024>>>();

    int sn = NB * (Na + Nq);
    scatter_kernel<<<(sn + 255) / 256, 256>>>(anchor, query, Na, Nq);

    dim3 ngrid((Nq * 4 + 255) / 256, NB);
    nn_kernel<<<ngrid, 256>>>(anchor, out, Nq, Na);

    dim3 fgrid(32, NB);
    fallback_kernel<<<fgrid, 128>>>(anchor, out, Nq, Na);
}